// round 8
// baseline (speedup 1.0000x reference)
#include <cuda_runtime.h>
#include <cstdint>

// Inverse 2D DWT, L=2, stride 2, pad 0: per input pixel a 2x2 butterfly.
//
// Block = 2 input rows (full width). Each thread: one (row, float2-col)
// position, loads all 4 planes (4x LDG.64, evict-first), computes the
// butterfly, writes results into an SMEM tile laid out exactly like the
// 4 contiguous output rows (8 KB). One cp.async.bulk store emits the whole
// tile as a single linear 8 KB GMEM write burst -> better DRAM write
// scheduling than per-lane 16B stores interleaved with 4 read streams.

__global__ void __launch_bounds__(256)
idwt2_l2_bulk_kernel(const float* __restrict__ low,
                     const float* __restrict__ highs,
                     const float* __restrict__ g0c_p,
                     const float* __restrict__ g1c_p,
                     const float* __restrict__ g0r_p,
                     const float* __restrict__ g1r_p,
                     float* __restrict__ out,
                     int NC, int H, int W)
{
    // 4 output rows x 2W floats, contiguous, matches GMEM layout.
    __shared__ __align__(128) float stile[4 * 512];

    const float a0 = __ldg(&g0c_p[0]), a1 = __ldg(&g0c_p[1]);
    const float b0 = __ldg(&g1c_p[0]), b1 = __ldg(&g1c_p[1]);
    const float c0 = __ldg(&g0r_p[0]), c1 = __ldg(&g0r_p[1]);
    const float d0 = __ldg(&g1r_p[0]), d1 = __ldg(&g1r_p[1]);

    const int W2 = W >> 1;                 // 128 float2 columns per input row
    const int H2 = H >> 1;                 // input row pairs

    // blockIdx.x encodes (nc, row-pair)
    const int i2 = blockIdx.x % H2;
    const int nc = blockIdx.x / H2;

    const int tid = threadIdx.x;
    const int r   = tid >> 7;              // 0/1: which input row of the pair
    const int c2  = tid & 127;             // float2 column
    const int i   = 2 * i2 + r;            // input row

    const long long plane = (long long)H * W;
    const long long off   = (long long)nc * plane + (long long)i * W + (long long)c2 * 2;
    const long long hb    = (long long)nc * 3 * plane + (long long)i * W + (long long)c2 * 2;

    const float2 ll = __ldcs((const float2*)(low   + off));
    const float2 lh = __ldcs((const float2*)(highs + hb));
    const float2 hl = __ldcs((const float2*)(highs + hb + plane));
    const float2 hh = __ldcs((const float2*)(highs + hb + 2 * plane));

    float4 r0, r1;                          // output rows 2i, 2i+1 (4 cols each)
    {   // input col j = 2*c2
        const float A0 = ll.x * a0 + lh.x * b0;
        const float B0 = hl.x * a0 + hh.x * b0;
        const float A1 = ll.x * a1 + lh.x * b1;
        const float B1 = hl.x * a1 + hh.x * b1;
        r0.x = A0 * c0 + B0 * d0;  r0.y = A0 * c1 + B0 * d1;
        r1.x = A1 * c0 + B1 * d0;  r1.y = A1 * c1 + B1 * d1;
    }
    {   // input col j = 2*c2 + 1
        const float A0 = ll.y * a0 + lh.y * b0;
        const float B0 = hl.y * a0 + hh.y * b0;
        const float A1 = ll.y * a1 + lh.y * b1;
        const float B1 = hl.y * a1 + hh.y * b1;
        r0.z = A0 * c0 + B0 * d0;  r0.w = A0 * c1 + B0 * d1;
        r1.z = A1 * c0 + B1 * d0;  r1.w = A1 * c1 + B1 * d1;
    }

    // SMEM tile rows: 2*r (=out row 2i within tile) and 2*r+1.
    const int scol = 4 * c2;
    *reinterpret_cast<float4*>(&stile[(2 * r)     * 512 + scol]) = r0;
    *reinterpret_cast<float4*>(&stile[(2 * r + 1) * 512 + scol]) = r1;

    __syncthreads();

    if (tid == 0) {
        // Make generic-proxy SMEM writes visible to the async proxy.
        asm volatile("fence.proxy.async.shared::cta;" ::: "memory");

        const int Wo = 2 * W;                               // 512
        float* gdst = out + (long long)nc * 4 * plane
                          + (long long)(4 * i2) * Wo;       // 4 contiguous rows

        uint32_t saddr;
        asm("{ .reg .u64 t; cvta.to.shared.u64 t, %1; cvt.u32.u64 %0, t; }"
            : "=r"(saddr) : "l"(stile));

        asm volatile(
            "cp.async.bulk.global.shared::cta.bulk_group [%0], [%1], %2;"
            :: "l"(gdst), "r"(saddr), "r"((int)(4 * 512 * sizeof(float)))
            : "memory");
        asm volatile("cp.async.bulk.commit_group;" ::: "memory");
        // Wait until SMEM has been fully read so the block may release it.
        asm volatile("cp.async.bulk.wait_group.read 0;" ::: "memory");
    }
}

extern "C" void kernel_launch(void* const* d_in, const int* in_sizes, int n_in,
                              void* d_out, int out_size)
{
    const float* low   = (const float*)d_in[0];
    const float* highs = (const float*)d_in[1];
    const float* g0c   = (const float*)d_in[2];
    const float* g1c   = (const float*)d_in[3];
    const float* g0r   = (const float*)d_in[4];
    const float* g1r   = (const float*)d_in[5];
    float* out = (float*)d_out;

    const int H = 256, W = 256;
    const int NC = in_sizes[0] / (H * W);

    const int blocks = NC * (H / 2);       // one block per input row pair
    idwt2_l2_bulk_kernel<<<blocks, 256>>>(low, highs, g0c, g1c, g0r, g1r,
                                          out, NC, H, W);
}

// round 9
// speedup vs baseline: 1.0086x; 1.0086x over previous
#include <cuda_runtime.h>

// Inverse 2D DWT, L=2 separable synthesis, stride 2, pad 0 -> per input
// pixel a 2x2 butterfly into the output.
//
// One thread per (row, float2-col) input position, all 4 planes:
//   4x LDG.64 loads, 2x STG.128 lane-contiguous streaming stores.
// Grid: (H*W/2/256, NC) -> no integer division anywhere; all 32-bit offsets.

__global__ void __launch_bounds__(256)
idwt2_l2_kernel(const float* __restrict__ low,
                const float* __restrict__ highs,
                const float* __restrict__ g0c_p,
                const float* __restrict__ g1c_p,
                const float* __restrict__ g0r_p,
                const float* __restrict__ g1r_p,
                float* __restrict__ out)
{
    constexpr int H  = 256, W = 256;
    constexpr int W2 = W / 2;              // 128 float2 columns
    constexpr int PLANE  = H * W;          // 65536
    constexpr int Wo     = 2 * W;          // 512
    constexpr int OPLANE = 4 * PLANE;      // 262144

    // Uniform filter taps (broadcast).
    const float a0 = __ldg(&g0c_p[0]), a1 = __ldg(&g0c_p[1]);
    const float b0 = __ldg(&g1c_p[0]), b1 = __ldg(&g1c_p[1]);
    const float c0 = __ldg(&g0r_p[0]), c1 = __ldg(&g0r_p[1]);
    const float d0 = __ldg(&g1r_p[0]), d1 = __ldg(&g1r_p[1]);

    const int nc  = blockIdx.y;
    const int pos = blockIdx.x * 256 + threadIdx.x;   // 0 .. H*W2-1
    const int i   = pos >> 7;                         // input row
    const int j2  = pos & 127;                        // float2 column

    const unsigned rowoff = (unsigned)i * W + (unsigned)(j2 << 1);
    const unsigned loff   = (unsigned)nc * PLANE + rowoff;
    const unsigned hb     = (unsigned)nc * (3 * PLANE) + rowoff;

    const float2 ll = *reinterpret_cast<const float2*>(low   + loff);
    const float2 lh = *reinterpret_cast<const float2*>(highs + hb);
    const float2 hl = *reinterpret_cast<const float2*>(highs + hb + PLANE);
    const float2 hh = *reinterpret_cast<const float2*>(highs + hb + 2 * PLANE);

    float4 r0, r1;
    {   // input col j = 2*j2
        const float A0 = ll.x * a0 + lh.x * b0;
        const float B0 = hl.x * a0 + hh.x * b0;
        const float A1 = ll.x * a1 + lh.x * b1;
        const float B1 = hl.x * a1 + hh.x * b1;
        r0.x = A0 * c0 + B0 * d0;  r0.y = A0 * c1 + B0 * d1;
        r1.x = A1 * c0 + B1 * d0;  r1.y = A1 * c1 + B1 * d1;
    }
    {   // input col j = 2*j2 + 1
        const float A0 = ll.y * a0 + lh.y * b0;
        const float B0 = hl.y * a0 + hh.y * b0;
        const float A1 = ll.y * a1 + lh.y * b1;
        const float B1 = hl.y * a1 + hh.y * b1;
        r0.z = A0 * c0 + B0 * d0;  r0.w = A0 * c1 + B0 * d1;
        r1.z = A1 * c0 + B1 * d0;  r1.w = A1 * c1 + B1 * d1;
    }

    const unsigned ooff = (unsigned)nc * OPLANE
                        + (unsigned)(2 * i) * Wo
                        + (unsigned)(j2 << 2);
    __stcs(reinterpret_cast<float4*>(out + ooff),      r0);   // row 2i
    __stcs(reinterpret_cast<float4*>(out + ooff + Wo), r1);   // row 2i+1
}

extern "C" void kernel_launch(void* const* d_in, const int* in_sizes, int n_in,
                              void* d_out, int out_size)
{
    const float* low   = (const float*)d_in[0];
    const float* highs = (const float*)d_in[1];
    const float* g0c   = (const float*)d_in[2];
    const float* g1c   = (const float*)d_in[3];
    const float* g0r   = (const float*)d_in[4];
    const float* g1r   = (const float*)d_in[5];
    float* out = (float*)d_out;

    const int H = 256, W = 256;
    const int NC = in_sizes[0] / (H * W);

    dim3 grid((H * (W / 2)) / 256, NC);    // (128, NC)
    idwt2_l2_kernel<<<grid, 256>>>(low, highs, g0c, g1c, g0r, g1r, out);
}

// round 12
// speedup vs baseline: 1.0213x; 1.0126x over previous
#include <cuda_runtime.h>

// Inverse 2D DWT, L=2 separable synthesis, stride 2, pad 0 -> per input
// pixel a 2x2 butterfly into the output.
//
// Blackwell 256-bit variant: one thread per (input row, float4-col-group).
//   Loads : 4x LDG.128 (one float4 per plane)   -> 16B/lane
//   Stores: 2x STG.256 (st.global.cs.v8.f32)    -> 32B/lane, one instr/row
// Grid (H*W/4/256, NC); no integer division; all 32-bit offsets.

__global__ void __launch_bounds__(256)
idwt2_l2_kernel(const float* __restrict__ low,
                const float* __restrict__ highs,
                const float* __restrict__ g0c_p,
                const float* __restrict__ g1c_p,
                const float* __restrict__ g0r_p,
                const float* __restrict__ g1r_p,
                float* __restrict__ out)
{
    constexpr int H  = 256, W = 256;
    constexpr int W4 = W / 4;              // 64 float4 column groups
    constexpr int PLANE  = H * W;          // 65536
    constexpr int Wo     = 2 * W;          // 512
    constexpr int OPLANE = 4 * PLANE;      // 262144

    // Uniform filter taps (broadcast).
    const float a0 = __ldg(&g0c_p[0]), a1 = __ldg(&g0c_p[1]);
    const float b0 = __ldg(&g1c_p[0]), b1 = __ldg(&g1c_p[1]);
    const float c0 = __ldg(&g0r_p[0]), c1 = __ldg(&g0r_p[1]);
    const float d0 = __ldg(&g1r_p[0]), d1 = __ldg(&g1r_p[1]);

    const int nc  = blockIdx.y;
    const int pos = blockIdx.x * 256 + threadIdx.x;   // 0 .. H*W4-1
    const int i   = pos >> 6;                         // input row
    const int j4  = pos & 63;                         // float4 column group

    const unsigned rowoff = (unsigned)i * W + (unsigned)(j4 << 2);
    const unsigned loff   = (unsigned)nc * PLANE + rowoff;
    const unsigned hb     = (unsigned)nc * (3 * PLANE) + rowoff;

    const float4 ll = *reinterpret_cast<const float4*>(low   + loff);
    const float4 lh = *reinterpret_cast<const float4*>(highs + hb);
    const float4 hl = *reinterpret_cast<const float4*>(highs + hb + PLANE);
    const float4 hh = *reinterpret_cast<const float4*>(highs + hb + 2 * PLANE);

    // r0[0..7]: output row 2i, cols 8*j4 .. 8*j4+7
    // r1[0..7]: output row 2i+1, same cols
    float r0[8], r1[8];

    #define COL(LLC, LHC, HLC, HHC, O)                                        \
    {                                                                         \
        const float A0 = (LLC) * a0 + (LHC) * b0;                             \
        const float B0 = (HLC) * a0 + (HHC) * b0;                             \
        const float A1 = (LLC) * a1 + (LHC) * b1;                             \
        const float B1 = (HLC) * a1 + (HHC) * b1;                             \
        r0[(O)]     = A0 * c0 + B0 * d0;  r0[(O) + 1] = A0 * c1 + B0 * d1;    \
        r1[(O)]     = A1 * c0 + B1 * d0;  r1[(O) + 1] = A1 * c1 + B1 * d1;    \
    }

    COL(ll.x, lh.x, hl.x, hh.x, 0)
    COL(ll.y, lh.y, hl.y, hh.y, 2)
    COL(ll.z, lh.z, hl.z, hh.z, 4)
    COL(ll.w, lh.w, hl.w, hh.w, 6)
    #undef COL

    const unsigned ooff = (unsigned)nc * OPLANE
                        + (unsigned)(2 * i) * Wo
                        + (unsigned)(j4 << 3);

    // 256-bit streaming stores (Blackwell STG.256).
    asm volatile(
        "st.global.cs.v8.f32 [%0], {%1, %2, %3, %4, %5, %6, %7, %8};"
        :: "l"(out + ooff),
           "f"(r0[0]), "f"(r0[1]), "f"(r0[2]), "f"(r0[3]),
           "f"(r0[4]), "f"(r0[5]), "f"(r0[6]), "f"(r0[7])
        : "memory");
    asm volatile(
        "st.global.cs.v8.f32 [%0], {%1, %2, %3, %4, %5, %6, %7, %8};"
        :: "l"(out + ooff + Wo),
           "f"(r1[0]), "f"(r1[1]), "f"(r1[2]), "f"(r1[3]),
           "f"(r1[4]), "f"(r1[5]), "f"(r1[6]), "f"(r1[7])
        : "memory");
}

extern "C" void kernel_launch(void* const* d_in, const int* in_sizes, int n_in,
                              void* d_out, int out_size)
{
    const float* low   = (const float*)d_in[0];
    const float* highs = (const float*)d_in[1];
    const float* g0c   = (const float*)d_in[2];
    const float* g1c   = (const float*)d_in[3];
    const float* g0r   = (const float*)d_in[4];
    const float* g1r   = (const float*)d_in[5];
    float* out = (float*)d_out;

    const int H = 256, W = 256;
    const int NC = in_sizes[0] / (H * W);

    dim3 grid((H * (W / 4)) / 256, NC);    // (64, NC)
    idwt2_l2_kernel<<<grid, 256>>>(low, highs, g0c, g1c, g0r, g1r, out);
}